// round 7
// baseline (speedup 1.0000x reference)
#include <cuda_runtime.h>
#include <cuda_fp16.h>
#include <cstdint>
#include <math.h>

#define HID    768
#define FFNDIM 3072
#define NE     8
#define TMAX   16384

// ---------------- scratch (device globals: allocation-free) ----------------
__device__ __half g_xh [TMAX * HID];            // fp16 X
__device__ __half g_w1h[NE * FFNDIM * HID];     // w1 transposed: [E][FFN][HID] fp16
__device__ __half g_w2h[NE * HID * FFNDIM];     // w2 transposed: [E][HID][FFN] fp16
__device__ __half g_Hh [2 * TMAX * FFNDIM];     // gelu(X@w1+b1) fp16
__device__ float  g_Y  [2 * TMAX * HID];        // H@w2+b2 per pair (fp32)
__device__ int    g_cnt[NE];
__device__ int    g_off[NE];
__device__ int    g_list[NE * TMAX];
__device__ int    g_pe  [2 * TMAX];
__device__ int    g_ps  [2 * TMAX];
__device__ float  g_pgate[2 * TMAX];
__device__ float  g_probsum[NE];
__device__ float  g_gatesum[NE];

// ---------------- helpers ----------------
__device__ __forceinline__ void cp16(uint32_t dst, const void* src) {
    asm volatile("cp.async.cg.shared.global [%0], [%1], 16;" :: "r"(dst), "l"(src));
}
__device__ __forceinline__ float fast_tanh(float y) {
    float t = __expf(2.0f * fminf(fabsf(y), 15.0f));
    float r = (t - 1.0f) / (t + 1.0f);
    return copysignf(r, y);
}
__device__ __forceinline__ float gelu_tanh(float x) {
    float x3 = x * x * x;
    return 0.5f * x * (1.0f + fast_tanh(0.7978845608028654f * (x + 0.044715f * x3)));
}

#define MMA16816(acc, a, b) \
    asm volatile( \
        "mma.sync.aligned.m16n8k16.row.col.f32.f16.f16.f32 " \
        "{%0,%1,%2,%3}, {%4,%5,%6,%7}, {%8,%9}, {%0,%1,%2,%3};\n" \
        : "+f"((acc)[0]), "+f"((acc)[1]), "+f"((acc)[2]), "+f"((acc)[3]) \
        : "r"((a)[0]), "r"((a)[1]), "r"((a)[2]), "r"((a)[3]), \
          "r"((b)[0]), "r"((b)[1]))

// ---------------- prep1: init + convert X + transpose w1 (fused) ----------------
__global__ void prep1_kernel(const float* __restrict__ x,
                             const float* __restrict__ w1, int T) {
    __shared__ float tile[32][33];
    int tx = threadIdx.x, ty = threadIdx.y;
    if (blockIdx.z < NE) {
        int e = blockIdx.z;
        const float* s = w1 + (size_t)e * HID * FFNDIM;
        __half* d = g_w1h + (size_t)e * HID * FFNDIM;
        int c0 = blockIdx.x * 32, r0 = blockIdx.y * 32;   // c in FFN, r in HID
        #pragma unroll
        for (int i = 0; i < 32; i += 8)
            tile[ty + i][tx] = s[(size_t)(r0 + ty + i) * FFNDIM + c0 + tx];
        __syncthreads();
        #pragma unroll
        for (int i = 0; i < 32; i += 8)
            d[(size_t)(c0 + ty + i) * HID + r0 + tx] = __float2half_rn(tile[tx][ty + i]);
    } else {
        int tid = ty * 32 + tx;
        int bid = blockIdx.y * gridDim.x + blockIdx.x;
        if (bid == 0 && tid < NE) {
            g_cnt[tid] = 0; g_probsum[tid] = 0.f; g_gatesum[tid] = 0.f;
        }
        int n = T * HID;
        int nb = gridDim.x * gridDim.y;
        for (int i = bid * 256 + tid; i < n; i += nb * 256)
            g_xh[i] = __float2half_rn(x[i]);
    }
}

// transpose w2: src[e][r][c] (R=FFNDIM, C=HID) -> g_w2h[e][c][r]
__global__ void prep2_kernel(const float* __restrict__ w2) {
    __shared__ float tile[32][33];
    int e = blockIdx.z;
    const float* s = w2 + (size_t)e * FFNDIM * HID;
    __half* d = g_w2h + (size_t)e * FFNDIM * HID;
    int c0 = blockIdx.x * 32, r0 = blockIdx.y * 32;
    int tx = threadIdx.x, ty = threadIdx.y;
    #pragma unroll
    for (int i = 0; i < 32; i += 8)
        tile[ty + i][tx] = s[(size_t)(r0 + ty + i) * HID + c0 + tx];
    __syncthreads();
    #pragma unroll
    for (int i = 0; i < 32; i += 8)
        d[(size_t)(c0 + ty + i) * FFNDIM + r0 + tx] = __float2half_rn(tile[tx][ty + i]);
}

// one warp per token
__global__ void __launch_bounds__(256) router_kernel(
    const float* __restrict__ x, const float* __restrict__ rw,
    const float* __restrict__ rb,
    float* __restrict__ out_rw, float* __restrict__ out_mask,
    float* __restrict__ out_logits, int T)
{
    __shared__ float srw[NE * HID];
    __shared__ float sprob[NE];
    __shared__ float sgate[NE];
    int tid = threadIdx.x;
    for (int i = tid; i < NE * HID; i += blockDim.x) {
        int e = i / HID, c = i - e * HID;
        srw[i] = rw[c * NE + e];
    }
    if (tid < NE) { sprob[tid] = 0.f; sgate[tid] = 0.f; }
    __syncthreads();

    int warp = tid >> 5, lane = tid & 31;
    int t = blockIdx.x * 8 + warp;
    if (t < T) {
        float p[NE];
        #pragma unroll
        for (int e = 0; e < NE; e++) p[e] = 0.f;
        const float* xr = x + (size_t)t * HID;
        for (int c = lane; c < HID; c += 32) {
            float xv = xr[c];
            #pragma unroll
            for (int e = 0; e < NE; e++) p[e] += xv * srw[e * HID + c];
        }
        #pragma unroll
        for (int e = 0; e < NE; e++) {
            #pragma unroll
            for (int o = 16; o > 0; o >>= 1)
                p[e] += __shfl_xor_sync(0xffffffffu, p[e], o);
        }
        if (lane == 0) {
            float lg[NE];
            #pragma unroll
            for (int e = 0; e < NE; e++) lg[e] = p[e] + rb[e];
            float m = lg[0];
            #pragma unroll
            for (int e = 1; e < NE; e++) m = fmaxf(m, lg[e]);
            float s = 0.f, pr[NE];
            #pragma unroll
            for (int e = 0; e < NE; e++) { pr[e] = expf(lg[e] - m); s += pr[e]; }
            float inv = 1.f / s;
            #pragma unroll
            for (int e = 0; e < NE; e++) {
                pr[e] *= inv;
                out_logits[(size_t)t * NE + e] = lg[e];
                out_rw[(size_t)t * NE + e] = pr[e];
                atomicAdd(&sprob[e], pr[e]);
            }
            int i1 = 0; float v1 = lg[0];
            #pragma unroll
            for (int e = 1; e < NE; e++) if (lg[e] > v1) { v1 = lg[e]; i1 = e; }
            int i2 = -1; float v2 = -3.4e38f;
            #pragma unroll
            for (int e = 0; e < NE; e++)
                if (e != i1 && lg[e] > v2) { v2 = lg[e]; i2 = e; }
            float texp = expf(v2 - v1);
            float gden = 1.f / (1.f + texp);
            float gg1 = gden, gg2 = texp * gden;
            #pragma unroll
            for (int e = 0; e < NE; e++) {
                float mv = (e == i1) ? gg1 : ((e == i2) ? gg2 : 0.f);
                out_mask[(size_t)t * NE + e] = mv;
            }
            int pos1 = atomicAdd(&g_cnt[i1], 1);
            g_list[i1 * TMAX + pos1] = t;
            g_pe[2 * t] = i1; g_ps[2 * t] = pos1; g_pgate[2 * t] = gg1;
            int pos2 = atomicAdd(&g_cnt[i2], 1);
            g_list[i2 * TMAX + pos2] = t;
            g_pe[2 * t + 1] = i2; g_ps[2 * t + 1] = pos2; g_pgate[2 * t + 1] = gg2;
            atomicAdd(&sgate[i1], gg1);
            atomicAdd(&sgate[i2], gg2);
        }
    }
    __syncthreads();
    if (tid < NE) {
        atomicAdd(&g_probsum[tid], sprob[tid]);
        atomicAdd(&g_gatesum[tid], sgate[tid]);
    }
}

__global__ void offsets_kernel(float* __restrict__ out_aux, int T) {
    if (threadIdx.x == 0 && blockIdx.x == 0) {
        int acc = 0;
        float aux = 0.f;
        #pragma unroll
        for (int e = 0; e < NE; e++) {
            g_off[e] = acc;
            acc += g_cnt[e];
            aux += g_probsum[e] * g_gatesum[e];
        }
        out_aux[0] = aux * (float)NE / ((float)T * (float)T);
    }
}

// ---------------- fp16 mma.sync grouped GEMM ----------------
// CTA tile 256(M) x 128(N), 256 threads = 8 warps as 4(M) x 2(N), warp tile 64x64.
// Halves LDS words per MAC vs 64x32 warp tiles -> tensor pipe no longer co-saturated
// with the L1/shared port. 4-stage cp.async ring, prefetch distance 2, ONE
// __syncthreads per k-tile (stage (kt+3)%4 written while stage kt%4 read: disjoint).
// EPI=1: A = gathered g_xh rows, B = g_w1h[E][FFN][HID], out = fp16(gelu(.+b1)) -> g_Hh
// EPI=2: A = g_Hh (contiguous),  B = g_w2h[E][HID][FFN], out = .+b2 -> g_Y (fp32)
#define BM      256
#define BN      128
#define BK      64
#define ROWH    72                    // padded row length in halves (144 B)
#define ROWB    144
#define TILEA_H (BM * ROWH)
#define TILEA_B (BM * ROWB)           // 36864 B
#define TILEB_B (BN * ROWB)           // 18432 B
#define STAGEB  (TILEA_B + TILEB_B)   // 55296 B
#define STAGEH  (STAGEB / 2)
#define NSTAGE  4

template<int KDIM, int NDIM, int EPI>
__global__ void __launch_bounds__(256, 1) gemmh_kernel(const float* __restrict__ bias)
{
    const int e   = blockIdx.z;
    const int cnt = g_cnt[e];
    const int m0  = blockIdx.y * BM;
    if (m0 >= cnt) return;
    const int n0  = blockIdx.x * BN;
    const int off = g_off[e];

    extern __shared__ __half smem[];
    const uint32_t SB = (uint32_t)__cvta_generic_to_shared(smem);

    const int tid  = threadIdx.x;
    const int lane = tid & 31;
    const int wid  = tid >> 5;          // 0..7
    const int wm   = wid >> 1;          // 0..3
    const int wn   = wid & 1;           // 0..1
    const int gid  = lane >> 2;         // 0..7
    const int tig  = lane & 3;          // 0..3

    // ---- cp.async plumbing: 8 A rows + 4 B rows per thread (16B chunks) ----
    const int chunk = tid & 7;          // 0..7  (16B = 8 halves)
    const int row4  = tid >> 3;         // 0..31
    const __half* abase = (EPI == 1 ? g_xh : g_Hh) + chunk * 8;
    const __half* bbase = (EPI == 1 ? g_w1h : g_w2h)
                          + (size_t)e * KDIM * NDIM + chunk * 8;
    uint32_t aoff[8], boff[4];          // element offsets (fit u32)
    uint32_t adst0, bdst0;
    #pragma unroll
    for (int i = 0; i < 8; i++) {
        int row = row4 + 32 * i;        // 0..255
        int slot = m0 + row;
        if (slot > cnt - 1) slot = cnt - 1;
        int arow = (EPI == 1) ? g_list[e * TMAX + slot] : (off + slot);
        aoff[i] = (uint32_t)arow * (uint32_t)KDIM;
    }
    #pragma unroll
    for (int i = 0; i < 4; i++) {
        int row = row4 + 32 * i;        // 0..127
        boff[i] = (uint32_t)(n0 + row) * (uint32_t)KDIM;
    }
    adst0 = SB + (uint32_t)(row4 * ROWB + chunk * 16);
    bdst0 = SB + TILEA_B + (uint32_t)(row4 * ROWB + chunk * 16);

    auto load_stage = [&](int s, int k0) {
        uint32_t so = (uint32_t)s * STAGEB;
        #pragma unroll
        for (int i = 0; i < 8; i++)
            cp16(adst0 + so + i * 32 * ROWB, abase + aoff[i] + k0);
        #pragma unroll
        for (int i = 0; i < 4; i++)
            cp16(bdst0 + so + i * 32 * ROWB, bbase + boff[i] + k0);
    };

    float acc[4][8][4];
    #pragma unroll
    for (int mi = 0; mi < 4; mi++)
        #pragma unroll
        for (int ni = 0; ni < 8; ni++)
            #pragma unroll
            for (int r = 0; r < 4; r++) acc[mi][ni][r] = 0.f;

    constexpr int NKT = KDIM / BK;
    load_stage(0, 0);
    asm volatile("cp.async.commit_group;" ::: "memory");
    load_stage(1, BK);
    asm volatile("cp.async.commit_group;" ::: "memory");

    const int mbase = wm * 64;
    const int nbase = wn * 64;

    for (int kt = 0; kt < NKT; kt++) {
        if (kt + 2 < NKT) load_stage((kt + 2) & 3, (kt + 2) * BK);
        asm volatile("cp.async.commit_group;" ::: "memory");
        asm volatile("cp.async.wait_group 2;" ::: "memory");
        __syncthreads();

        const __half* as = smem + (size_t)(kt & 3) * STAGEH;
        const __half* bs = as + TILEA_H;
        #pragma unroll
        for (int kk = 0; kk < BK; kk += 16) {
            uint32_t a[4][4], b[8][2];
            #pragma unroll
            for (int mi = 0; mi < 4; mi++) {
                const int r = mbase + mi * 16 + gid;
                const int kc = kk + 2 * tig;
                a[mi][0] = *(const uint32_t*)(as + r * ROWH + kc);
                a[mi][1] = *(const uint32_t*)(as + (r + 8) * ROWH + kc);
                a[mi][2] = *(const uint32_t*)(as + r * ROWH + kc + 8);
                a[mi][3] = *(const uint32_t*)(as + (r + 8) * ROWH + kc + 8);
            }
            #pragma unroll
            for (int ni = 0; ni < 8; ni++) {
                const int nrow = nbase + ni * 8 + gid;
                const int kc = kk + 2 * tig;
                b[ni][0] = *(const uint32_t*)(bs + nrow * ROWH + kc);
                b[ni][1] = *(const uint32_t*)(bs + nrow * ROWH + kc + 8);
            }
            #pragma unroll
            for (int mi = 0; mi < 4; mi++)
                #pragma unroll
                for (int ni = 0; ni < 8; ni++)
                    MMA16816(acc[mi][ni], a[mi], b[ni]);
        }
    }

    // ---- epilogue ----
    #pragma unroll
    for (int ni = 0; ni < 8; ni++) {
        int cc = n0 + wn * 64 + ni * 8 + 2 * tig;
        float bv0 = bias[e * NDIM + cc];
        float bv1 = bias[e * NDIM + cc + 1];
        #pragma unroll
        for (int mi = 0; mi < 4; mi++) {
            int r = m0 + wm * 64 + mi * 16 + gid;
            #pragma unroll
            for (int h = 0; h < 2; h++) {
                int rr = r + h * 8;
                if (rr < cnt) {
                    float v0 = acc[mi][ni][2 * h]     + bv0;
                    float v1 = acc[mi][ni][2 * h + 1] + bv1;
                    if (EPI == 1) {
                        __half2 hv = __floats2half2_rn(gelu_tanh(v0), gelu_tanh(v1));
                        *reinterpret_cast<__half2*>(
                            &g_Hh[(size_t)(off + rr) * NDIM + cc]) = hv;
                    } else {
                        float2 st; st.x = v0; st.y = v1;
                        *reinterpret_cast<float2*>(
                            &g_Y[(size_t)(off + rr) * NDIM + cc]) = st;
                    }
                }
            }
        }
    }
}

__global__ void combine_kernel(float* __restrict__ out, int T) {
    int total = T * (HID / 4);
    for (int i = blockIdx.x * blockDim.x + threadIdx.x; i < total;
         i += gridDim.x * blockDim.x) {
        int t = i / (HID / 4);
        int c = i - t * (HID / 4);
        int p0 = g_off[g_pe[2 * t]]     + g_ps[2 * t];
        int p1 = g_off[g_pe[2 * t + 1]] + g_ps[2 * t + 1];
        float gg0 = g_pgate[2 * t], gg1 = g_pgate[2 * t + 1];
        const float4 a = *reinterpret_cast<const float4*>(&g_Y[(size_t)p0 * HID + 4 * c]);
        const float4 b = *reinterpret_cast<const float4*>(&g_Y[(size_t)p1 * HID + 4 * c]);
        float4 o;
        o.x = gg0 * a.x + gg1 * b.x;
        o.y = gg0 * a.y + gg1 * b.y;
        o.z = gg0 * a.z + gg1 * b.z;
        o.w = gg0 * a.w + gg1 * b.w;
        reinterpret_cast<float4*>(out)[i] = o;
    }
}

// ---------------- launch ----------------
extern "C" void kernel_launch(void* const* d_in, const int* in_sizes, int n_in,
                              void* d_out, int out_size)
{
    const float* x  = (const float*)d_in[0];
    const float* rw = (const float*)d_in[1];
    const float* rb = (const float*)d_in[2];
    const float* w1 = (const float*)d_in[3];
    const float* b1 = (const float*)d_in[4];
    const float* w2 = (const float*)d_in[5];
    const float* b2 = (const float*)d_in[6];
    int T = in_sizes[0] / HID;
    if (T > TMAX) T = TMAX;

    float* out        = (float*)d_out;
    float* out_comb   = out;
    float* out_rw     = out + (size_t)T * HID;
    float* out_mask   = out_rw + (size_t)T * NE;
    float* out_aux    = out_mask + (size_t)T * NE;
    float* out_logits = out_aux + 1;

    const int smem = NSTAGE * STAGEB;   // 221184 B
    cudaFuncSetAttribute(gemmh_kernel<HID, FFNDIM, 1>,
                         cudaFuncAttributeMaxDynamicSharedMemorySize, smem);
    cudaFuncSetAttribute(gemmh_kernel<FFNDIM, HID, 2>,
                         cudaFuncAttributeMaxDynamicSharedMemorySize, smem);

    // launch order puts gemm1 at slot #4 for the fixed-slot ncu capture
    prep1_kernel<<<dim3(FFNDIM / 32, HID / 32, NE + 1), dim3(32, 8)>>>(x, w1, T);
    router_kernel<<<(T + 7) / 8, 256>>>(x, rw, rb, out_rw, out_mask, out_logits, T);
    offsets_kernel<<<1, 32>>>(out_aux, T);

    int mt = (T + BM - 1) / BM;
    gemmh_kernel<HID, FFNDIM, 1><<<dim3(FFNDIM / BN, mt, NE), 256, smem>>>(b1);
    prep2_kernel<<<dim3(HID / 32, FFNDIM / 32, NE), dim3(32, 8)>>>(w2);
    gemmh_kernel<FFNDIM, HID, 2><<<dim3(HID / BN, mt, NE), 256, smem>>>(b2);

    combine_kernel<<<4096, 256>>>(out_comb, T);
}

// round 8
// speedup vs baseline: 1.1666x; 1.1666x over previous
#include <cuda_runtime.h>
#include <cuda_fp16.h>
#include <cstdint>
#include <math.h>

#define HID    768
#define FFNDIM 3072
#define NE     8
#define TMAX   16384

// ---------------- scratch (device globals: allocation-free) ----------------
__device__ __half g_xh [TMAX * HID];            // fp16 X
__device__ __half g_w1h[NE * FFNDIM * HID];     // w1 transposed: [E][FFN][HID] fp16
__device__ __half g_w2h[NE * HID * FFNDIM];     // w2 transposed: [E][HID][FFN] fp16
__device__ __half g_Hh [2 * TMAX * FFNDIM];     // gelu(X@w1+b1) fp16
__device__ float  g_Y  [2 * TMAX * HID];        // H@w2+b2 per pair (fp32)
__device__ int    g_cnt[NE];
__device__ int    g_off[NE];
__device__ int    g_list[NE * TMAX];
__device__ int    g_pe  [2 * TMAX];
__device__ int    g_ps  [2 * TMAX];
__device__ float  g_pgate[2 * TMAX];
__device__ float  g_probsum[NE];
__device__ float  g_gatesum[NE];

// ---------------- helpers ----------------
__device__ __forceinline__ void cp16(uint32_t dst, const void* src) {
    asm volatile("cp.async.cg.shared.global [%0], [%1], 16;" :: "r"(dst), "l"(src));
}
__device__ __forceinline__ float fast_tanh(float y) {
    float t = __expf(2.0f * fminf(fabsf(y), 15.0f));
    float r = (t - 1.0f) / (t + 1.0f);
    return copysignf(r, y);
}
__device__ __forceinline__ float gelu_tanh(float x) {
    float x3 = x * x * x;
    return 0.5f * x * (1.0f + fast_tanh(0.7978845608028654f * (x + 0.044715f * x3)));
}

#define LDSM4(r0, r1, r2, r3, addr) \
    asm volatile("ldmatrix.sync.aligned.m8n8.x4.shared.b16 {%0,%1,%2,%3}, [%4];" \
                 : "=r"(r0), "=r"(r1), "=r"(r2), "=r"(r3) : "r"(addr))

#define MMA16816(acc, a, b) \
    asm volatile( \
        "mma.sync.aligned.m16n8k16.row.col.f32.f16.f16.f32 " \
        "{%0,%1,%2,%3}, {%4,%5,%6,%7}, {%8,%9}, {%0,%1,%2,%3};\n" \
        : "+f"((acc)[0]), "+f"((acc)[1]), "+f"((acc)[2]), "+f"((acc)[3]) \
        : "r"((a)[0]), "r"((a)[1]), "r"((a)[2]), "r"((a)[3]), \
          "r"((b)[0]), "r"((b)[1]))

// ---------------- prep1: init + convert X + transpose w1 (fused) ----------------
__global__ void prep1_kernel(const float* __restrict__ x,
                             const float* __restrict__ w1, int T) {
    __shared__ float tile[32][33];
    int tx = threadIdx.x, ty = threadIdx.y;
    if (blockIdx.z < NE) {
        int e = blockIdx.z;
        const float* s = w1 + (size_t)e * HID * FFNDIM;
        __half* d = g_w1h + (size_t)e * HID * FFNDIM;
        int c0 = blockIdx.x * 32, r0 = blockIdx.y * 32;   // c in FFN, r in HID
        #pragma unroll
        for (int i = 0; i < 32; i += 8)
            tile[ty + i][tx] = s[(size_t)(r0 + ty + i) * FFNDIM + c0 + tx];
        __syncthreads();
        #pragma unroll
        for (int i = 0; i < 32; i += 8)
            d[(size_t)(c0 + ty + i) * HID + r0 + tx] = __float2half_rn(tile[tx][ty + i]);
    } else {
        int tid = ty * 32 + tx;
        int bid = blockIdx.y * gridDim.x + blockIdx.x;
        if (bid == 0 && tid < NE) {
            g_cnt[tid] = 0; g_probsum[tid] = 0.f; g_gatesum[tid] = 0.f;
        }
        int n = T * HID;
        int nb = gridDim.x * gridDim.y;
        for (int i = bid * 256 + tid; i < n; i += nb * 256)
            g_xh[i] = __float2half_rn(x[i]);
    }
}

// transpose w2: src[e][r][c] (R=FFNDIM, C=HID) -> g_w2h[e][c][r]
__global__ void prep2_kernel(const float* __restrict__ w2) {
    __shared__ float tile[32][33];
    int e = blockIdx.z;
    const float* s = w2 + (size_t)e * FFNDIM * HID;
    __half* d = g_w2h + (size_t)e * FFNDIM * HID;
    int c0 = blockIdx.x * 32, r0 = blockIdx.y * 32;
    int tx = threadIdx.x, ty = threadIdx.y;
    #pragma unroll
    for (int i = 0; i < 32; i += 8)
        tile[ty + i][tx] = s[(size_t)(r0 + ty + i) * HID + c0 + tx];
    __syncthreads();
    #pragma unroll
    for (int i = 0; i < 32; i += 8)
        d[(size_t)(c0 + ty + i) * FFNDIM + r0 + tx] = __float2half_rn(tile[tx][ty + i]);
}

// one warp per token
__global__ void __launch_bounds__(256) router_kernel(
    const float* __restrict__ x, const float* __restrict__ rw,
    const float* __restrict__ rb,
    float* __restrict__ out_rw, float* __restrict__ out_mask,
    float* __restrict__ out_logits, int T)
{
    __shared__ float srw[NE * HID];
    __shared__ float sprob[NE];
    __shared__ float sgate[NE];
    int tid = threadIdx.x;
    for (int i = tid; i < NE * HID; i += blockDim.x) {
        int e = i / HID, c = i - e * HID;
        srw[i] = rw[c * NE + e];
    }
    if (tid < NE) { sprob[tid] = 0.f; sgate[tid] = 0.f; }
    __syncthreads();

    int warp = tid >> 5, lane = tid & 31;
    int t = blockIdx.x * 8 + warp;
    if (t < T) {
        float p[NE];
        #pragma unroll
        for (int e = 0; e < NE; e++) p[e] = 0.f;
        const float* xr = x + (size_t)t * HID;
        for (int c = lane; c < HID; c += 32) {
            float xv = xr[c];
            #pragma unroll
            for (int e = 0; e < NE; e++) p[e] += xv * srw[e * HID + c];
        }
        #pragma unroll
        for (int e = 0; e < NE; e++) {
            #pragma unroll
            for (int o = 16; o > 0; o >>= 1)
                p[e] += __shfl_xor_sync(0xffffffffu, p[e], o);
        }
        if (lane == 0) {
            float lg[NE];
            #pragma unroll
            for (int e = 0; e < NE; e++) lg[e] = p[e] + rb[e];
            float m = lg[0];
            #pragma unroll
            for (int e = 1; e < NE; e++) m = fmaxf(m, lg[e]);
            float s = 0.f, pr[NE];
            #pragma unroll
            for (int e = 0; e < NE; e++) { pr[e] = expf(lg[e] - m); s += pr[e]; }
            float inv = 1.f / s;
            #pragma unroll
            for (int e = 0; e < NE; e++) {
                pr[e] *= inv;
                out_logits[(size_t)t * NE + e] = lg[e];
                out_rw[(size_t)t * NE + e] = pr[e];
                atomicAdd(&sprob[e], pr[e]);
            }
            int i1 = 0; float v1 = lg[0];
            #pragma unroll
            for (int e = 1; e < NE; e++) if (lg[e] > v1) { v1 = lg[e]; i1 = e; }
            int i2 = -1; float v2 = -3.4e38f;
            #pragma unroll
            for (int e = 0; e < NE; e++)
                if (e != i1 && lg[e] > v2) { v2 = lg[e]; i2 = e; }
            float texp = expf(v2 - v1);
            float gden = 1.f / (1.f + texp);
            float gg1 = gden, gg2 = texp * gden;
            #pragma unroll
            for (int e = 0; e < NE; e++) {
                float mv = (e == i1) ? gg1 : ((e == i2) ? gg2 : 0.f);
                out_mask[(size_t)t * NE + e] = mv;
            }
            int pos1 = atomicAdd(&g_cnt[i1], 1);
            g_list[i1 * TMAX + pos1] = t;
            g_pe[2 * t] = i1; g_ps[2 * t] = pos1; g_pgate[2 * t] = gg1;
            int pos2 = atomicAdd(&g_cnt[i2], 1);
            g_list[i2 * TMAX + pos2] = t;
            g_pe[2 * t + 1] = i2; g_ps[2 * t + 1] = pos2; g_pgate[2 * t + 1] = gg2;
            atomicAdd(&sgate[i1], gg1);
            atomicAdd(&sgate[i2], gg2);
        }
    }
    __syncthreads();
    if (tid < NE) {
        atomicAdd(&g_probsum[tid], sprob[tid]);
        atomicAdd(&g_gatesum[tid], sgate[tid]);
    }
}

__global__ void offsets_kernel(float* __restrict__ out_aux, int T) {
    if (threadIdx.x == 0 && blockIdx.x == 0) {
        int acc = 0;
        float aux = 0.f;
        #pragma unroll
        for (int e = 0; e < NE; e++) {
            g_off[e] = acc;
            acc += g_cnt[e];
            aux += g_probsum[e] * g_gatesum[e];
        }
        out_aux[0] = aux * (float)NE / ((float)T * (float)T);
    }
}

// ---------------- fp16 mma.sync grouped GEMM (ldmatrix fragments) ----------------
// CTA tile 256(M) x 128(N) x 64(K), 512 threads = 16 warps (4x4), warp tile 64x32.
// Same pipeline as round-6 winner (4-stage ring, prefetch dist 2, single sync);
// fragment loads switched from 96 scalar LDS.32 to 24 ldmatrix.x4 per warp/k-tile.
// Lane maps follow the documented ldmatrix distribution (lane l of each 8x8 row l%8,
// register order = lane-group order) and reproduce the verified scalar map.
// EPI=1: A = gathered g_xh rows, B = g_w1h[E][FFN][HID], out = fp16(gelu(.+b1)) -> g_Hh
// EPI=2: A = g_Hh (contiguous),  B = g_w2h[E][HID][FFN], out = .+b2 -> g_Y (fp32)
#define BM      256
#define BN      128
#define BK      64
#define ROWH    72                    // padded row length in halves (144 B)
#define ROWB    144
#define TILEA_H (BM * ROWH)
#define TILEA_B (BM * ROWB)           // 36864 B
#define TILEB_B (BN * ROWB)           // 18432 B
#define STAGEB  (TILEA_B + TILEB_B)   // 55296 B
#define NSTAGE  4

template<int KDIM, int NDIM, int EPI>
__global__ void __launch_bounds__(512, 1) gemmh_kernel(const float* __restrict__ bias)
{
    const int e   = blockIdx.z;
    const int cnt = g_cnt[e];
    const int m0  = blockIdx.y * BM;
    if (m0 >= cnt) return;
    const int n0  = blockIdx.x * BN;
    const int off = g_off[e];

    extern __shared__ __half smem[];
    const uint32_t SB = (uint32_t)__cvta_generic_to_shared(smem);

    const int tid  = threadIdx.x;
    const int lane = tid & 31;
    const int wid  = tid >> 5;
    const int wm   = wid >> 2;          // 0..3
    const int wn   = wid & 3;           // 0..3
    const int gid  = lane >> 2;         // 0..7
    const int tig  = lane & 3;          // 0..3

    // ---- cp.async plumbing: 4 A rows + 2 B rows per thread (16B chunks) ----
    const int chunk = tid & 7;          // 0..7  (16B = 8 halves)
    const int row4  = tid >> 3;         // 0..63
    const __half* asrc[4];
    const __half* bsrc[2];
    uint32_t adst[4], bdst[2];
    const __half* wT = (EPI == 1 ? g_w1h : g_w2h) + (size_t)e * KDIM * NDIM;
    #pragma unroll
    for (int i = 0; i < 4; i++) {
        int row = row4 + 64 * i;        // 0..255
        int slot = m0 + row;
        if (slot > cnt - 1) slot = cnt - 1;
        if (EPI == 1) {
            int tok = g_list[e * TMAX + slot];
            asrc[i] = g_xh + (size_t)tok * KDIM + chunk * 8;
        } else {
            asrc[i] = g_Hh + (size_t)(off + slot) * KDIM + chunk * 8;
        }
        adst[i] = SB + (uint32_t)(row * ROWB + chunk * 16);
    }
    #pragma unroll
    for (int i = 0; i < 2; i++) {
        int row = row4 + 64 * i;        // 0..127
        bsrc[i] = wT + (size_t)(n0 + row) * KDIM + chunk * 8;
        bdst[i] = SB + TILEA_B + (uint32_t)(row * ROWB + chunk * 16);
    }

    auto load_stage = [&](int s, int k0) {
        uint32_t so = (uint32_t)s * STAGEB;
        #pragma unroll
        for (int i = 0; i < 4; i++) cp16(adst[i] + so, asrc[i] + k0);
        #pragma unroll
        for (int i = 0; i < 2; i++) cp16(bdst[i] + so, bsrc[i] + k0);
    };

    float acc[4][4][4];
    #pragma unroll
    for (int mi = 0; mi < 4; mi++)
        #pragma unroll
        for (int ni = 0; ni < 4; ni++)
            #pragma unroll
            for (int r = 0; r < 4; r++) acc[mi][ni][r] = 0.f;

    constexpr int NKT = KDIM / BK;
    load_stage(0, 0);
    asm volatile("cp.async.commit_group;" ::: "memory");
    load_stage(1, BK);
    asm volatile("cp.async.commit_group;" ::: "memory");

    const int mbase = wm * 64;
    const int nbase = wn * 32;

    // ---- per-lane ldmatrix byte offsets ----
    // lane group g = lane>>3 (0..3), lr = lane&7.
    // A x4 tile at (row base R, col kk): matrices {R+lr,kk} {R+8+lr,kk} {R+lr,kk+8} {R+8+lr,kk+8}
    const int lgrp = lane >> 3, lr = lane & 7;
    const uint32_t a_lane = (uint32_t)((((lgrp & 1) * 8 + lr) * ROWH + (lgrp >> 1) * 8) * 2);
    // B x4 tile at (row base N16, col kk): matrices {N16+lr,kk} {N16+lr,kk+8} {N16+8+lr,kk} {N16+8+lr,kk+8}
    const uint32_t b_lane = (uint32_t)((((lgrp >> 1) * 8 + lr) * ROWH + (lgrp & 1) * 8) * 2);

    for (int kt = 0; kt < NKT; kt++) {
        if (kt + 2 < NKT) load_stage((kt + 2) & 3, (kt + 2) * BK);
        asm volatile("cp.async.commit_group;" ::: "memory");
        asm volatile("cp.async.wait_group 2;" ::: "memory");
        __syncthreads();

        const uint32_t stage = SB + (uint32_t)(kt & 3) * STAGEB;
        const uint32_t asb = stage + (uint32_t)(mbase * ROWB) + a_lane;
        const uint32_t bsb = stage + TILEA_B + (uint32_t)(nbase * ROWB) + b_lane;
        #pragma unroll
        for (int kk = 0; kk < BK; kk += 16) {
            uint32_t a[4][4], b[4][2];
            #pragma unroll
            for (int mi = 0; mi < 4; mi++)
                LDSM4(a[mi][0], a[mi][1], a[mi][2], a[mi][3],
                      asb + (uint32_t)(mi * 16 * ROWB + kk * 2));
            #pragma unroll
            for (int p = 0; p < 2; p++)
                LDSM4(b[2 * p][0], b[2 * p][1], b[2 * p + 1][0], b[2 * p + 1][1],
                      bsb + (uint32_t)(p * 16 * ROWB + kk * 2));
            #pragma unroll
            for (int mi = 0; mi < 4; mi++)
                #pragma unroll
                for (int ni = 0; ni < 4; ni++)
                    MMA16816(acc[mi][ni], a[mi], b[ni]);
        }
    }

    // ---- epilogue ----
    #pragma unroll
    for (int ni = 0; ni < 4; ni++) {
        int cc = n0 + wn * 32 + ni * 8 + 2 * tig;
        float bv0 = bias[e * NDIM + cc];
        float bv1 = bias[e * NDIM + cc + 1];
        #pragma unroll
        for (int mi = 0; mi < 4; mi++) {
            int r = m0 + wm * 64 + mi * 16 + gid;
            #pragma unroll
            for (int h = 0; h < 2; h++) {
                int rr = r + h * 8;
                if (rr < cnt) {
                    float v0 = acc[mi][ni][2 * h]     + bv0;
                    float v1 = acc[mi][ni][2 * h + 1] + bv1;
                    if (EPI == 1) {
                        __half2 hv = __floats2half2_rn(gelu_tanh(v0), gelu_tanh(v1));
                        *reinterpret_cast<__half2*>(
                            &g_Hh[(size_t)(off + rr) * NDIM + cc]) = hv;
                    } else {
                        float2 st; st.x = v0; st.y = v1;
                        *reinterpret_cast<float2*>(
                            &g_Y[(size_t)(off + rr) * NDIM + cc]) = st;
                    }
                }
            }
        }
    }
}

__global__ void combine_kernel(float* __restrict__ out, int T) {
    int total = T * (HID / 4);
    for (int i = blockIdx.x * blockDim.x + threadIdx.x; i < total;
         i += gridDim.x * blockDim.x) {
        int t = i / (HID / 4);
        int c = i - t * (HID / 4);
        int p0 = g_off[g_pe[2 * t]]     + g_ps[2 * t];
        int p1 = g_off[g_pe[2 * t + 1]] + g_ps[2 * t + 1];
        float gg0 = g_pgate[2 * t], gg1 = g_pgate[2 * t + 1];
        const float4 a = *reinterpret_cast<const float4*>(&g_Y[(size_t)p0 * HID + 4 * c]);
        const float4 b = *reinterpret_cast<const float4*>(&g_Y[(size_t)p1 * HID + 4 * c]);
        float4 o;
        o.x = gg0 * a.x + gg1 * b.x;
        o.y = gg0 * a.y + gg1 * b.y;
        o.z = gg0 * a.z + gg1 * b.z;
        o.w = gg0 * a.w + gg1 * b.w;
        reinterpret_cast<float4*>(out)[i] = o;
    }
}

// ---------------- launch ----------------
extern "C" void kernel_launch(void* const* d_in, const int* in_sizes, int n_in,
                              void* d_out, int out_size)
{
    const float* x  = (const float*)d_in[0];
    const float* rw = (const float*)d_in[1];
    const float* rb = (const float*)d_in[2];
    const float* w1 = (const float*)d_in[3];
    const float* b1 = (const float*)d_in[4];
    const float* w2 = (const float*)d_in[5];
    const float* b2 = (const float*)d_in[6];
    int T = in_sizes[0] / HID;
    if (T > TMAX) T = TMAX;

    float* out        = (float*)d_out;
    float* out_comb   = out;
    float* out_rw     = out + (size_t)T * HID;
    float* out_mask   = out_rw + (size_t)T * NE;
    float* out_aux    = out_mask + (size_t)T * NE;
    float* out_logits = out_aux + 1;

    const int smem = NSTAGE * STAGEB;   // 221184 B
    cudaFuncSetAttribute(gemmh_kernel<HID, FFNDIM, 1>,
                         cudaFuncAttributeMaxDynamicSharedMemorySize, smem);
    cudaFuncSetAttribute(gemmh_kernel<FFNDIM, HID, 2>,
                         cudaFuncAttributeMaxDynamicSharedMemorySize, smem);

    // launch order puts gemm1 at slot #4 for the fixed-slot ncu capture
    prep1_kernel<<<dim3(FFNDIM / 32, HID / 32, NE + 1), dim3(32, 8)>>>(x, w1, T);
    router_kernel<<<(T + 7) / 8, 256>>>(x, rw, rb, out_rw, out_mask, out_logits, T);
    offsets_kernel<<<1, 32>>>(out_aux, T);

    int mt = (T + BM - 1) / BM;
    gemmh_kernel<HID, FFNDIM, 1><<<dim3(FFNDIM / BN, mt, NE), 512, smem>>>(b1);
    prep2_kernel<<<dim3(HID / 32, FFNDIM / 32, NE), dim3(32, 8)>>>(w2);
    gemmh_kernel<FFNDIM, HID, 2><<<dim3(HID / BN, mt, NE), 512, smem>>>(b2);

    combine_kernel<<<4096, 256>>>(out_comb, T);
}